// round 1
// baseline (speedup 1.0000x reference)
#include <cuda_runtime.h>
#include <math.h>

#define C 1000          // NUM_CLASSES
#define B 1024          // BATCH
#define TPB 256
#define EPS 1e-4f
#define BETA 0.7f
#define LAMBDA1 3.0f

// ---- block reduction helpers -------------------------------------------------
__device__ __forceinline__ float block_reduce_sum(float val) {
    __shared__ float sh[8];
    __shared__ float res;
    __syncthreads();                       // protect shared reuse across calls
    int lane = threadIdx.x & 31;
    int wid  = threadIdx.x >> 5;
    #pragma unroll
    for (int o = 16; o > 0; o >>= 1) val += __shfl_xor_sync(0xffffffffu, val, o);
    if (lane == 0) sh[wid] = val;
    __syncthreads();
    if (wid == 0) {
        float v = (lane < (TPB >> 5)) ? sh[lane] : 0.0f;
        #pragma unroll
        for (int o = 4; o > 0; o >>= 1) v += __shfl_xor_sync(0xffu, v, o);
        if (lane == 0) res = v;
    }
    __syncthreads();
    return res;
}

__device__ __forceinline__ float block_reduce_max(float val) {
    __shared__ float sh[8];
    __shared__ float res;
    __syncthreads();
    int lane = threadIdx.x & 31;
    int wid  = threadIdx.x >> 5;
    #pragma unroll
    for (int o = 16; o > 0; o >>= 1)
        val = fmaxf(val, __shfl_xor_sync(0xffffffffu, val, o));
    if (lane == 0) sh[wid] = val;
    __syncthreads();
    if (wid == 0) {
        float v = (lane < (TPB >> 5)) ? sh[lane] : -INFINITY;
        #pragma unroll
        for (int o = 4; o > 0; o >>= 1)
            v = fmaxf(v, __shfl_xor_sync(0xffu, v, o));
        if (lane == 0) res = v;
    }
    __syncthreads();
    return res;
}

// ---- one block per batch row -------------------------------------------------
__global__ void __launch_bounds__(TPB)
elr_row_kernel(const float* __restrict__ output,
               const float* __restrict__ target,
               const int*   __restrict__ label,
               const int*   __restrict__ index,
               float*       __restrict__ out)   // out[0]=loss, out[1..]=new_target
{
    const int r = blockIdx.x;
    const int t = threadIdx.x;
    const float* orow = output + (size_t)r * C;

    // each thread owns up to 4 class slots: c = t + i*TPB
    float v[4];
    #pragma unroll
    for (int i = 0; i < 4; i++) {
        int c = t + i * TPB;
        v[i] = (c < C) ? orow[c] : -INFINITY;
    }

    // 1) row max
    float m = fmaxf(fmaxf(v[0], v[1]), fmaxf(v[2], v[3]));
    m = block_reduce_max(m);

    // 2) sum of exp
    float e[4];
    float s = 0.0f;
    #pragma unroll
    for (int i = 0; i < 4; i++) {
        int c = t + i * TPB;
        e[i] = (c < C) ? expf(v[i] - m) : 0.0f;
        s += e[i];
    }
    const float S = block_reduce_sum(s);
    const float inv_S = 1.0f / S;
    const float lse = m + logf(S);          // logsumexp for CE

    // 3) clipped softmax + its sum (for renormalized detached preds)
    float yp[4];
    float cs = 0.0f;
    #pragma unroll
    for (int i = 0; i < 4; i++) {
        int c = t + i * TPB;
        if (c < C) {
            yp[i] = fminf(fmaxf(e[i] * inv_S, EPS), 1.0f - EPS);
            cs += yp[i];
        } else {
            yp[i] = 0.0f;
        }
    }
    const float inv_cs = 1.0f / block_reduce_sum(cs);

    // 4) EMA row update + dot(new_row, y_pred)
    const int start = (*index) * B;
    const float* trow = target + (size_t)(start + r) * C;
    float* outrow = out + 1 + (size_t)(start + r) * C;

    float dot = 0.0f;
    #pragma unroll
    for (int i = 0; i < 4; i++) {
        int c = t + i * TPB;
        if (c < C) {
            float nt = BETA * trow[c] + (1.0f - BETA) * (yp[i] * inv_cs);
            outrow[c] = nt;
            dot += nt * yp[i];
        }
    }
    const float D = block_reduce_sum(dot);

    // 5) per-row loss contribution
    if (t == 0) {
        const int l = label[r];
        const float ce  = -(orow[l] - lse);
        const float elr = logf(1.0f - D);
        atomicAdd(out, (ce + LAMBDA1 * elr) * (1.0f / (float)B));
    }
}

extern "C" void kernel_launch(void* const* d_in, const int* in_sizes, int n_in,
                              void* d_out, int out_size) {
    const float* output = (const float*)d_in[0];
    const float* target = (const float*)d_in[1];
    const int*   label  = (const int*)  d_in[2];
    const int*   index  = (const int*)  d_in[3];
    float* out = (float*)d_out;

    const size_t target_elems = (size_t)in_sizes[1];   // 200,000,000

    // loss accumulator slot -> 0
    cudaMemsetAsync(out, 0, sizeof(float), 0);
    // bulk copy: new_target == target except 1024 rows (overwritten by kernel)
    cudaMemcpyAsync(out + 1, target, target_elems * sizeof(float),
                    cudaMemcpyDeviceToDevice, 0);
    // per-row softmax/EMA/loss; overwrites the modified slice inside d_out
    elr_row_kernel<<<B, TPB, 0, 0>>>(output, target, label, index, out);
}

// round 2
// speedup vs baseline: 1.7930x; 1.7930x over previous
#include <cuda_runtime.h>
#include <math.h>

#define C 1000          // NUM_CLASSES
#define B 1024          // BATCH
#define TPB 256
#define EPS 1e-4f
#define BETA 0.7f
#define LAMBDA1 3.0f

#define N_TGT 200000000ull              // NUM_EXAMP * NUM_CLASSES
#define COPY_BLOCKS 2048
#define TOTAL_BLOCKS (B + COPY_BLOCKS)

// ---- block reduction helpers -------------------------------------------------
__device__ __forceinline__ float block_reduce_sum(float val) {
    __shared__ float sh[8];
    __shared__ float res;
    __syncthreads();
    int lane = threadIdx.x & 31;
    int wid  = threadIdx.x >> 5;
    #pragma unroll
    for (int o = 16; o > 0; o >>= 1) val += __shfl_xor_sync(0xffffffffu, val, o);
    if (lane == 0) sh[wid] = val;
    __syncthreads();
    if (wid == 0) {
        float v = (lane < (TPB >> 5)) ? sh[lane] : 0.0f;
        #pragma unroll
        for (int o = 4; o > 0; o >>= 1) v += __shfl_xor_sync(0xffu, v, o);
        if (lane == 0) res = v;
    }
    __syncthreads();
    return res;
}

__device__ __forceinline__ float block_reduce_max(float val) {
    __shared__ float sh[8];
    __shared__ float res;
    __syncthreads();
    int lane = threadIdx.x & 31;
    int wid  = threadIdx.x >> 5;
    #pragma unroll
    for (int o = 16; o > 0; o >>= 1)
        val = fmaxf(val, __shfl_xor_sync(0xffffffffu, val, o));
    if (lane == 0) sh[wid] = val;
    __syncthreads();
    if (wid == 0) {
        float v = (lane < (TPB >> 5)) ? sh[lane] : -INFINITY;
        #pragma unroll
        for (int o = 4; o > 0; o >>= 1)
            v = fmaxf(v, __shfl_xor_sync(0xffu, v, o));
        if (lane == 0) res = v;
    }
    __syncthreads();
    return res;
}

// ---- per-row softmax/EMA/loss (blocks 0..B-1) --------------------------------
__device__ void row_work(const float* __restrict__ output,
                         const float* __restrict__ target,
                         const int*   __restrict__ label,
                         int start,
                         float*       __restrict__ out)
{
    const int r = blockIdx.x;
    const int t = threadIdx.x;
    const float* orow = output + (size_t)r * C;

    float v[4];
    #pragma unroll
    for (int i = 0; i < 4; i++) {
        int c = t + i * TPB;
        v[i] = (c < C) ? orow[c] : -INFINITY;
    }

    float m = fmaxf(fmaxf(v[0], v[1]), fmaxf(v[2], v[3]));
    m = block_reduce_max(m);

    float e[4];
    float s = 0.0f;
    #pragma unroll
    for (int i = 0; i < 4; i++) {
        int c = t + i * TPB;
        e[i] = (c < C) ? expf(v[i] - m) : 0.0f;
        s += e[i];
    }
    const float S = block_reduce_sum(s);
    const float inv_S = 1.0f / S;
    const float lse = m + logf(S);

    float yp[4];
    float cs = 0.0f;
    #pragma unroll
    for (int i = 0; i < 4; i++) {
        int c = t + i * TPB;
        if (c < C) {
            yp[i] = fminf(fmaxf(e[i] * inv_S, EPS), 1.0f - EPS);
            cs += yp[i];
        } else {
            yp[i] = 0.0f;
        }
    }
    const float inv_cs = 1.0f / block_reduce_sum(cs);

    const float* trow = target + (size_t)(start + r) * C;
    float* outrow = out + 1 + (size_t)(start + r) * C;

    float dot = 0.0f;
    #pragma unroll
    for (int i = 0; i < 4; i++) {
        int c = t + i * TPB;
        if (c < C) {
            float nt = BETA * trow[c] + (1.0f - BETA) * (yp[i] * inv_cs);
            outrow[c] = nt;
            dot += nt * yp[i];
        }
    }
    const float D = block_reduce_sum(dot);

    if (t == 0) {
        const int l = label[r];
        const float ce  = -(orow[l] - lse);
        const float elr = logf(1.0f - D);
        atomicAdd(out, (ce + LAMBDA1 * elr) * (1.0f / (float)B));
    }
}

// ---- bulk copy target -> out+1, skipping the EMA slice (blocks B..) ----------
__device__ void copy_work(const float* __restrict__ tgt,
                          size_t s_beg,          // slice start (elem idx in target)
                          float* __restrict__ out)
{
    const size_t s_end = s_beg + (size_t)B * C;   // slice end (exclusive)

    // head: target[0..2] -> out[1..3]
    // tail: target[N_TGT-1] -> out[N_TGT]
    if (blockIdx.x == B && threadIdx.x < 4) {
        size_t j = (threadIdx.x < 3) ? (size_t)threadIdx.x : (N_TGT - 1);
        if (j < s_beg || j >= s_end) out[1 + j] = tgt[j];
    }

    // aligned chunks: chunk k covers target elems j = 3+4k .. 6+4k,
    // stored to out+4+4k (16B-aligned since out is malloc'd base).
    const size_t NCHUNKS = (N_TGT - 4) / 4;   // 49,999,999
    const size_t tid    = (size_t)(blockIdx.x - B) * TPB + threadIdx.x;
    const size_t stride = (size_t)COPY_BLOCKS * TPB;

    for (size_t k = tid; k < NCHUNKS; k += stride) {
        const size_t j = 3 + 4 * k;
        // fast path: fully inside slice -> skip (no loads needed)
        if (j >= s_beg && j + 4 <= s_end) continue;

        float a = __ldg(tgt + j);
        float b = __ldg(tgt + j + 1);
        float c = __ldg(tgt + j + 2);
        float d = __ldg(tgt + j + 3);

        if (j + 4 <= s_beg || j >= s_end) {
            // fully outside slice: vector store
            *reinterpret_cast<float4*>(out + 1 + j) = make_float4(a, b, c, d);
        } else {
            // partial overlap (at most 2 chunks total): per-element
            if (j     < s_beg || j     >= s_end) out[1 + j    ] = a;
            if (j + 1 < s_beg || j + 1 >= s_end) out[2 + j    ] = b;
            if (j + 2 < s_beg || j + 2 >= s_end) out[3 + j    ] = c;
            if (j + 3 < s_beg || j + 3 >= s_end) out[4 + j    ] = d;
        }
    }
}

__global__ void __launch_bounds__(TPB)
elr_fused_kernel(const float* __restrict__ output,
                 const float* __restrict__ target,
                 const int*   __restrict__ label,
                 const int*   __restrict__ index,
                 float*       __restrict__ out)
{
    const int start = (*index) * B;
    if (blockIdx.x < B) {
        row_work(output, target, label, start, out);
    } else {
        copy_work(target, (size_t)start * C, out);
    }
}

extern "C" void kernel_launch(void* const* d_in, const int* in_sizes, int n_in,
                              void* d_out, int out_size) {
    const float* output = (const float*)d_in[0];
    const float* target = (const float*)d_in[1];
    const int*   label  = (const int*)  d_in[2];
    const int*   index  = (const int*)  d_in[3];
    float* out = (float*)d_out;

    // loss accumulator slot -> 0
    cudaMemsetAsync(out, 0, sizeof(float), 0);
    // fused: per-row softmax/EMA/loss + SM-side bulk copy
    elr_fused_kernel<<<TOTAL_BLOCKS, TPB, 0, 0>>>(output, target, label, index, out);
}